// round 3
// baseline (speedup 1.0000x reference)
#include <cuda_runtime.h>
#include <math.h>

#define TT 4096
#define DD 2048
#define FFDIM 8192
#define EE 8

// ---------------- device scratch (no allocations allowed) ----------------
__device__ float g_H[(size_t)TT * FFDIM];   // 128 MB intermediate activations (sorted rows)
__device__ int   g_idx[TT];
__device__ float g_w[TT];
__device__ int   g_counts[EE];
__device__ int   g_offsets[EE];
__device__ int   g_rank[TT];
__device__ int   g_perm[TT];

// ---------------- packed f32x2 helpers (Blackwell) ----------------
__device__ __forceinline__ unsigned long long pack2(float v) {
    unsigned long long r;
    asm("mov.b64 %0, {%1, %1};" : "=l"(r) : "f"(v));
    return r;
}
__device__ __forceinline__ void ffma2(unsigned long long& d, unsigned long long a, unsigned long long b) {
    asm("fma.rn.f32x2 %0, %1, %2, %0;" : "+l"(d) : "l"(a), "l"(b));
}
__device__ __forceinline__ float2 unpack2(unsigned long long v) {
    float2 f;
    asm("mov.b64 {%0, %1}, %2;" : "=f"(f.x), "=f"(f.y) : "l"(v));
    return f;
}

__device__ __forceinline__ float gelu_exact(float v) {
    return 0.5f * v * (1.0f + erff(v * 0.70710678118654752440f));
}

// ---------------- router: logits -> softmax top-1 weight + argmax ----------------
__global__ void zero_counts_kernel() {
    if (threadIdx.x < EE) g_counts[threadIdx.x] = 0;
}

__global__ void router_kernel(const float* __restrict__ x, const float* __restrict__ Wr) {
    const int t = blockIdx.x;
    const int warp = threadIdx.x >> 5;
    const int lane = threadIdx.x & 31;
    const float* xr = x + (size_t)t * DD;
    const float* wr = Wr + (size_t)warp * DD;
    float acc = 0.0f;
    for (int d = lane * 4; d < DD; d += 32 * 4) {
        float4 xv = *(const float4*)(xr + d);
        float4 wv = *(const float4*)(wr + d);
        acc += xv.x * wv.x + xv.y * wv.y + xv.z * wv.z + xv.w * wv.w;
    }
    #pragma unroll
    for (int o = 16; o; o >>= 1) acc += __shfl_xor_sync(0xFFFFFFFFu, acc, o);
    __shared__ float slog[EE];
    if (lane == 0) slog[warp] = acc;
    __syncthreads();
    if (threadIdx.x == 0) {
        float mx = slog[0]; int mi = 0;
        #pragma unroll
        for (int e = 1; e < EE; e++) if (slog[e] > mx) { mx = slog[e]; mi = e; }
        float s = 0.0f;
        #pragma unroll
        for (int e = 0; e < EE; e++) s += expf(slog[e] - mx);
        g_idx[t] = mi;
        g_w[t] = 1.0f / s;                       // max softmax prob
        g_rank[t] = atomicAdd(&g_counts[mi], 1);
    }
}

__global__ void scan_kernel() {
    int s = 0;
    #pragma unroll
    for (int e = 0; e < EE; e++) { g_offsets[e] = s; s += g_counts[e]; }
}

__global__ void scatter_kernel() {
    int t = blockIdx.x * blockDim.x + threadIdx.x;
    if (t < TT) g_perm[g_offsets[g_idx[t]] + g_rank[t]] = t;
}

// ---------------- grouped GEMM, 128x128x8 SIMT tiles, f32x2 FMA ----------------
// MODE 0:  H[sortpos, :] = gelu( x[perm[sortpos], :] @ W1[e] )   (K=DD, N=FFDIM)
// MODE 1:  out[perm[sortpos], :] = ( H[sortpos, :] @ W2[e] ) * w  (K=FFDIM, N=DD)
constexpr int BM = 128, BN = 128, BK = 8;

template<int MODE>
__global__ __launch_bounds__(256, 2) void moe_gemm(
    const float* __restrict__ Ag,   // x for MODE 0, unused for MODE 1
    const float* __restrict__ Bg,   // W1 or W2
    float* __restrict__ Cg)         // unused for MODE 0, out for MODE 1
{
    constexpr int K  = (MODE == 0) ? DD : FFDIM;
    constexpr int NN = (MODE == 0) ? FFDIM : DD;

    const int e   = blockIdx.z;
    const int cnt = g_counts[e];
    const int m0  = blockIdx.y * BM;
    if (m0 >= cnt) return;                    // uniform early exit (before any sync)
    const int off = g_offsets[e];
    const int n0  = blockIdx.x * BN;

    __shared__ float As[2][BK][BM];
    __shared__ float Bs[2][BK][BN];

    const int tid  = threadIdx.x;
    const int aRow = tid >> 1;
    const int aK   = (tid & 1) * 4;
    const int bK   = tid >> 5;
    const int bCol = (tid & 31) * 4;

    const int  rowIdx   = m0 + aRow;
    const bool rowValid = rowIdx < cnt;

    const float* aPtr;
    if (MODE == 0) {
        const int tok = rowValid ? g_perm[off + rowIdx] : 0;
        aPtr = Ag + (size_t)tok * DD + aK;
    } else {
        const int r = rowValid ? (off + rowIdx) : 0;
        aPtr = g_H + (size_t)r * FFDIM + aK;
    }
    const float* bPtr = Bg + (size_t)e * ((size_t)K * NN) + (size_t)bK * NN + n0 + bCol;

    const int tx = tid & 15, ty = tid >> 4;

    unsigned long long acc[8][4];
    #pragma unroll
    for (int i = 0; i < 8; i++)
        #pragma unroll
        for (int j = 0; j < 4; j++) acc[i][j] = 0ull;

    float4 aReg = rowValid ? *(const float4*)aPtr : make_float4(0.f, 0.f, 0.f, 0.f);
    float4 bReg = *(const float4*)bPtr;

    As[0][aK + 0][aRow] = aReg.x;
    As[0][aK + 1][aRow] = aReg.y;
    As[0][aK + 2][aRow] = aReg.z;
    As[0][aK + 3][aRow] = aReg.w;
    *(float4*)&Bs[0][bK][bCol] = bReg;
    __syncthreads();

    const int KT = K / BK;
    int buf = 0;
    for (int kt = 0; kt < KT; kt++) {
        if (kt + 1 < KT) {   // prefetch next global tile into regs (overlaps compute)
            aReg = rowValid ? *(const float4*)(aPtr + (kt + 1) * BK)
                            : make_float4(0.f, 0.f, 0.f, 0.f);
            bReg = *(const float4*)(bPtr + (size_t)(kt + 1) * BK * NN);
        }
        #pragma unroll
        for (int kk = 0; kk < BK; kk++) {
            float4 a0 = *(const float4*)&As[buf][kk][ty * 8];
            float4 a1 = *(const float4*)&As[buf][kk][ty * 8 + 4];
            ulonglong2 b01 = *(const ulonglong2*)&Bs[buf][kk][tx * 8];
            ulonglong2 b23 = *(const ulonglong2*)&Bs[buf][kk][tx * 8 + 4];
            unsigned long long bb0 = b01.x, bb1 = b01.y, bb2 = b23.x, bb3 = b23.y;
            float av[8] = {a0.x, a0.y, a0.z, a0.w, a1.x, a1.y, a1.z, a1.w};
            #pragma unroll
            for (int i = 0; i < 8; i++) {
                unsigned long long ap2 = pack2(av[i]);
                ffma2(acc[i][0], ap2, bb0);
                ffma2(acc[i][1], ap2, bb1);
                ffma2(acc[i][2], ap2, bb2);
                ffma2(acc[i][3], ap2, bb3);
            }
        }
        if (kt + 1 < KT) {
            buf ^= 1;
            As[buf][aK + 0][aRow] = aReg.x;
            As[buf][aK + 1][aRow] = aReg.y;
            As[buf][aK + 2][aRow] = aReg.z;
            As[buf][aK + 3][aRow] = aReg.w;
            *(float4*)&Bs[buf][bK][bCol] = bReg;
        }
        __syncthreads();
    }

    // ---------------- epilogue ----------------
    #pragma unroll
    for (int i = 0; i < 8; i++) {
        const int r = m0 + ty * 8 + i;
        if (r >= cnt) continue;
        float vals[8];
        #pragma unroll
        for (int j = 0; j < 4; j++) {
            float2 v = unpack2(acc[i][j]);
            vals[2 * j]     = v.x;
            vals[2 * j + 1] = v.y;
        }
        if (MODE == 0) {
            float* cp = g_H + (size_t)(off + r) * FFDIM + n0 + tx * 8;
            #pragma unroll
            for (int j = 0; j < 8; j++) vals[j] = gelu_exact(vals[j]);
            *(float4*)(cp)     = make_float4(vals[0], vals[1], vals[2], vals[3]);
            *(float4*)(cp + 4) = make_float4(vals[4], vals[5], vals[6], vals[7]);
        } else {
            const int tok = g_perm[off + r];
            const float s = g_w[tok];
            float* cp = Cg + (size_t)tok * DD + n0 + tx * 8;
            #pragma unroll
            for (int j = 0; j < 8; j++) vals[j] *= s;
            *(float4*)(cp)     = make_float4(vals[0], vals[1], vals[2], vals[3]);
            *(float4*)(cp + 4) = make_float4(vals[4], vals[5], vals[6], vals[7]);
        }
    }
}

// ---------------- launch ----------------
extern "C" void kernel_launch(void* const* d_in, const int* in_sizes, int n_in,
                              void* d_out, int out_size) {
    const float* x  = (const float*)d_in[0];
    const float* Wr = (const float*)d_in[1];
    const float* W1 = (const float*)d_in[2];
    const float* W2 = (const float*)d_in[3];
    float* out = (float*)d_out;

    zero_counts_kernel<<<1, 32>>>();
    router_kernel<<<TT, 256>>>(x, Wr);
    scan_kernel<<<1, 1>>>();
    scatter_kernel<<<TT / 256, 256>>>();

    dim3 g1(FFDIM / BN, TT / BM, EE);
    moe_gemm<0><<<g1, 256>>>(x, W1, nullptr);

    dim3 g2(DD / BN, TT / BM, EE);
    moe_gemm<1><<<g2, 256>>>(nullptr, W2, out);
}

// round 7
// speedup vs baseline: 2.2497x; 2.2497x over previous
#include <cuda_runtime.h>
#include <cuda_bf16.h>
#include <math.h>
#include <stdint.h>

#define TT 4096
#define DD 2048
#define FFDIM 8192
#define EE 8
#define MTILES 16   // covers up to 2048 tokens/expert (mean 512)

// ---------------- device scratch ----------------
__device__ float g_H[(size_t)TT * FFDIM];
__device__ int   g_idx[TT];
__device__ float g_w[TT];
__device__ int   g_counts[EE];
__device__ int   g_offsets[EE];
__device__ int   g_rank[TT];
__device__ int   g_perm[TT];

// ---------------- helpers ----------------
__device__ __forceinline__ uint32_t smem_u32(const void* p) {
    uint32_t a;
    asm("{ .reg .u64 t; cvta.to.shared.u64 t, %1; cvt.u32.u64 %0, t; }" : "=r"(a) : "l"(p));
    return a;
}
__device__ __forceinline__ uint32_t sw128(uint32_t b) { return b ^ ((b >> 3) & 0x70); }

// split fp32 pair -> bf16x2 hi + bf16x2 lo (f0 in low half, f1 in high half)
__device__ __forceinline__ void split2(float f0, float f1, uint32_t& hi, uint32_t& lo) {
    uint32_t h;
    asm("cvt.rn.bf16x2.f32 %0, %1, %2;" : "=r"(h) : "f"(f1), "f"(f0));
    float h0 = __uint_as_float(h << 16);
    float h1 = __uint_as_float(h & 0xFFFF0000u);
    float l0 = f0 - h0, l1 = f1 - h1;
    uint32_t l;
    asm("cvt.rn.bf16x2.f32 %0, %1, %2;" : "=r"(l) : "f"(l1), "f"(l0));
    hi = h; lo = l;
}

__device__ __forceinline__ void ldm4(uint32_t* r, uint32_t addr) {
    asm volatile("ldmatrix.sync.aligned.m8n8.x4.shared.b16 {%0,%1,%2,%3}, [%4];"
        : "=r"(r[0]), "=r"(r[1]), "=r"(r[2]), "=r"(r[3]) : "r"(addr));
}

__device__ __forceinline__ void mma_bf16(float* d, const uint32_t* a, uint32_t b0, uint32_t b1) {
    asm volatile("mma.sync.aligned.m16n8k16.row.col.f32.bf16.bf16.f32 "
        "{%0,%1,%2,%3}, {%4,%5,%6,%7}, {%8,%9}, {%0,%1,%2,%3};"
        : "+f"(d[0]), "+f"(d[1]), "+f"(d[2]), "+f"(d[3])
        : "r"(a[0]), "r"(a[1]), "r"(a[2]), "r"(a[3]), "r"(b0), "r"(b1));
}

__device__ __forceinline__ float gelu_exact(float v) {
    return 0.5f * v * (1.0f + erff(v * 0.70710678118654752440f));
}

// ---------------- router pipeline ----------------
__global__ void zero_counts_kernel() { if (threadIdx.x < EE) g_counts[threadIdx.x] = 0; }

__global__ void router_kernel(const float* __restrict__ x, const float* __restrict__ Wr) {
    const int t = blockIdx.x;
    const int warp = threadIdx.x >> 5, lane = threadIdx.x & 31;
    const float* xr = x + (size_t)t * DD;
    const float* wr = Wr + (size_t)warp * DD;
    float acc = 0.0f;
    for (int d = lane * 4; d < DD; d += 128) {
        float4 xv = *(const float4*)(xr + d);
        float4 wv = *(const float4*)(wr + d);
        acc += xv.x * wv.x + xv.y * wv.y + xv.z * wv.z + xv.w * wv.w;
    }
    #pragma unroll
    for (int o = 16; o; o >>= 1) acc += __shfl_xor_sync(0xFFFFFFFFu, acc, o);
    __shared__ float slog[EE];
    if (lane == 0) slog[warp] = acc;
    __syncthreads();
    if (threadIdx.x == 0) {
        float mx = slog[0]; int mi = 0;
        #pragma unroll
        for (int e = 1; e < EE; e++) if (slog[e] > mx) { mx = slog[e]; mi = e; }
        float s = 0.0f;
        #pragma unroll
        for (int e = 0; e < EE; e++) s += expf(slog[e] - mx);
        g_idx[t] = mi;
        g_w[t] = 1.0f / s;
        g_rank[t] = atomicAdd(&g_counts[mi], 1);
    }
}

__global__ void scan_kernel() {
    int s = 0;
    #pragma unroll
    for (int e = 0; e < EE; e++) { g_offsets[e] = s; s += g_counts[e]; }
}

__global__ void scatter_kernel() {
    int t = blockIdx.x * blockDim.x + threadIdx.x;
    if (t < TT) g_perm[g_offsets[g_idx[t]] + g_rank[t]] = t;
}

// ---------------- mma.sync grouped GEMM (split-bf16 3-pass) ----------------
// MODE 0: H[srow,:] = gelu( x[perm,:] @ W1[e] )     K=DD,   N=FFDIM
// MODE 1: out[tok,:] = ( H[srow,:] @ W2[e] ) * w     K=FFDIM, N=DD
constexpr int BM = 128, BN = 128, BKS = 64;
constexpr int TILE_BYTES = BM * BKS * 2;         // 16 KB per bf16 tile
constexpr int BUF_BYTES  = 4 * TILE_BYTES;       // Ahi, Alo, Bhi, Blo
constexpr int SMEM_TOTAL = 2 * BUF_BYTES;        // 128 KB double-buffered

template<int MODE>
__global__ __launch_bounds__(256, 1) void moe_gemm_mma(
    const float* __restrict__ Ag, const float* __restrict__ Bg, float* __restrict__ Cg)
{
    constexpr int K  = (MODE == 0) ? DD : FFDIM;
    constexpr int NN = (MODE == 0) ? FFDIM : DD;
    constexpr int KT = K / BKS;

    const int e   = blockIdx.z;
    const int cnt = g_counts[e];
    const int m0  = blockIdx.x * BM;             // m fastest -> B tile L2 reuse
    if (m0 >= cnt) return;
    const int off = g_offsets[e];
    const int n0  = blockIdx.y * BN;

    extern __shared__ __align__(1024) char smem[];
    const uint32_t su = smem_u32(smem);
    const int tid = threadIdx.x, wid = tid >> 5, lane = tid & 31;

    // ---- staging geometry ----
    // A: thread owns 8 (m, k4) units: m = (tid>>4) + 16*i, k4 = tid&15
    const float* aRow[8];
    uint32_t sAoff[8];
    {
        const int mB = tid >> 4, k4 = tid & 15;
        #pragma unroll
        for (int i = 0; i < 8; i++) {
            int m = mB + 16 * i;
            int r = m0 + m;
            bool v = r < cnt;
            const float* base;
            if (MODE == 0) {
                int tok = v ? g_perm[off + r] : g_perm[off];
                base = Ag + (size_t)tok * DD;
            } else {
                base = g_H + (size_t)(off + (v ? r : 0)) * FFDIM;
            }
            aRow[i]  = base + k4 * 4;
            sAoff[i] = sw128((uint32_t)(m * 128 + k4 * 8));
        }
    }
    // B: thread owns n-row rB = tid&127, 8 k-groups with stagger (conflict break)
    const int rB = tid & 127;
    const float* bCol = Bg + (size_t)e * ((size_t)K * NN) + (size_t)(n0 + rB);
    int kkB[8]; uint32_t sBoff[8];
    {
        const int gB = tid >> 7, stag = (rB >> 3) & 3;
        #pragma unroll
        for (int i = 0; i < 8; i++) {
            int g = ((gB + 2 * i) + stag) & 15;
            kkB[i]   = g * 4;
            sBoff[i] = sw128((uint32_t)(rB * 128 + g * 8));
        }
    }

    // ---- ldmatrix geometry: warp (wm, wn) owns 32(m) x 64(n) ----
    const int wm = wid & 3, wn = wid >> 2;
    uint32_t aB[2], bB[4];
    #pragma unroll
    for (int c = 0; c < 2; c++) {
        int row = wm * 32 + c * 16 + (lane & 15);
        aB[c] = (uint32_t)(row * 128 + (lane >> 4) * 16);
    }
    #pragma unroll
    for (int j = 0; j < 4; j++) {
        int row = wn * 64 + j * 16 + (lane & 15);
        bB[j] = (uint32_t)(row * 128 + (lane >> 4) * 16);
    }

    float acc[2][8][4];
    #pragma unroll
    for (int c = 0; c < 2; c++)
        #pragma unroll
        for (int j = 0; j < 8; j++)
            #pragma unroll
            for (int q = 0; q < 4; q++) acc[c][j][q] = 0.0f;

    float4 pa[8], pb[8];

    auto preload = [&](int kt) {
        const int k0 = kt * BKS;
        #pragma unroll
        for (int i = 0; i < 8; i++) pa[i] = *(const float4*)(aRow[i] + k0);
        #pragma unroll
        for (int i = 0; i < 8; i++) {
            const float* p = bCol + (size_t)(k0 + kkB[i]) * NN;
            pb[i] = make_float4(p[0], p[(size_t)NN], p[(size_t)2 * NN], p[(size_t)3 * NN]);
        }
    };

    auto store_stage = [&](int b) {
        char* Ahi = smem + b * BUF_BYTES;
        char* Alo = Ahi + TILE_BYTES;
        char* Bhi = Alo + TILE_BYTES;
        char* Blo = Bhi + TILE_BYTES;
        #pragma unroll
        for (int i = 0; i < 8; i++) {
            uint32_t h0, l0, h1, l1;
            split2(pa[i].x, pa[i].y, h0, l0);
            split2(pa[i].z, pa[i].w, h1, l1);
            *(uint2*)(Ahi + sAoff[i]) = make_uint2(h0, h1);
            *(uint2*)(Alo + sAoff[i]) = make_uint2(l0, l1);
        }
        #pragma unroll
        for (int i = 0; i < 8; i++) {
            uint32_t h0, l0, h1, l1;
            split2(pb[i].x, pb[i].y, h0, l0);
            split2(pb[i].z, pb[i].w, h1, l1);
            *(uint2*)(Bhi + sBoff[i]) = make_uint2(h0, h1);
            *(uint2*)(Blo + sBoff[i]) = make_uint2(l0, l1);
        }
    };

    preload(0);
    store_stage(0);
    __syncthreads();

    for (int kt = 0; kt < KT; kt++) {
        const int buf = kt & 1;
        const bool more = (kt + 1 < KT);
        if (more) preload(kt + 1);          // LDGs overlap the MMA section

        const uint32_t baseA  = su + buf * BUF_BYTES;
        const uint32_t baseAl = baseA + TILE_BYTES;
        const uint32_t baseB  = baseA + 2 * TILE_BYTES;
        const uint32_t baseBl = baseA + 3 * TILE_BYTES;

        #pragma unroll
        for (int ks = 0; ks < 4; ks++) {
            uint32_t ah[2][4], al[2][4];
            #pragma unroll
            for (int c = 0; c < 2; c++) {
                uint32_t o = sw128(aB[c] + ks * 32);
                ldm4(ah[c], baseA  + o);
                ldm4(al[c], baseAl + o);
            }
            #pragma unroll
            for (int j = 0; j < 4; j++) {
                uint32_t bh[4], bl[4];
                uint32_t o = sw128(bB[j] + ks * 32);
                ldm4(bh, baseB  + o);
                ldm4(bl, baseBl + o);
                #pragma unroll
                for (int c = 0; c < 2; c++) {
                    mma_bf16(acc[c][2 * j],     ah[c], bh[0], bh[2]);
                    mma_bf16(acc[c][2 * j],     ah[c], bl[0], bl[2]);
                    mma_bf16(acc[c][2 * j],     al[c], bh[0], bh[2]);
                    mma_bf16(acc[c][2 * j + 1], ah[c], bh[1], bh[3]);
                    mma_bf16(acc[c][2 * j + 1], ah[c], bl[1], bl[3]);
                    mma_bf16(acc[c][2 * j + 1], al[c], bh[1], bh[3]);
                }
            }
        }
        if (more) store_stage(buf ^ 1);
        __syncthreads();
    }

    // ---------------- epilogue (register accumulators -> gmem) ----------------
    const int mw = m0 + wm * 32;
    const int nw = n0 + wn * 64;
    #pragma unroll
    for (int c = 0; c < 2; c++) {
        #pragma unroll
        for (int half = 0; half < 2; half++) {
            const int r = mw + c * 16 + (lane >> 2) + half * 8;
            if (r >= cnt) continue;
            float s = 0.0f; float* cp;
            if (MODE == 0) {
                cp = g_H + (size_t)(off + r) * FFDIM + nw;
            } else {
                const int tok = g_perm[off + r];
                s = g_w[tok];
                cp = Cg + (size_t)tok * DD + nw;
            }
            #pragma unroll
            for (int j = 0; j < 8; j++) {
                float v0 = acc[c][j][half * 2];
                float v1 = acc[c][j][half * 2 + 1];
                if (MODE == 0) { v0 = gelu_exact(v0); v1 = gelu_exact(v1); }
                else           { v0 *= s; v1 *= s; }
                *(float2*)(cp + j * 8 + (lane & 3) * 2) = make_float2(v0, v1);
            }
        }
    }
}

// ---------------- launch ----------------
extern "C" void kernel_launch(void* const* d_in, const int* in_sizes, int n_in,
                              void* d_out, int out_size) {
    const float* x  = (const float*)d_in[0];
    const float* Wr = (const float*)d_in[1];
    const float* W1 = (const float*)d_in[2];
    const float* W2 = (const float*)d_in[3];
    float* out = (float*)d_out;

    cudaFuncSetAttribute(moe_gemm_mma<0>, cudaFuncAttributeMaxDynamicSharedMemorySize, SMEM_TOTAL);
    cudaFuncSetAttribute(moe_gemm_mma<1>, cudaFuncAttributeMaxDynamicSharedMemorySize, SMEM_TOTAL);

    zero_counts_kernel<<<1, 32>>>();
    router_kernel<<<TT, 256>>>(x, Wr);
    scan_kernel<<<1, 1>>>();
    scatter_kernel<<<TT / 256, 256>>>();

    dim3 g1(MTILES, FFDIM / BN, EE);
    moe_gemm_mma<0><<<g1, 256, SMEM_TOTAL>>>(x, W1, nullptr);

    dim3 g2(MTILES, DD / BN, EE);
    moe_gemm_mma<1><<<g2, 256, SMEM_TOTAL>>>(nullptr, W2, out);
}